// round 8
// baseline (speedup 1.0000x reference)
#include <cuda_runtime.h>
#include <math.h>

#define N_CLUS 64
#define C_DIM 768
#define B_DIM 8
#define H_IN 32
#define HW 1024                          // 32*32
#define OUT_HW 512
#define PLANE (OUT_HW * OUT_HW)          // 262144
#define NPIX (B_DIM * HW)                // 8192
#define RES_ELEMS ((size_t)B_DIM * N_CLUS * PLANE)   // 134217728
#define CODE_ELEMS ((size_t)B_DIM * C_DIM * HW)      // 6291456
#define KC 32

#define FILL_BLOCKS 2048                 // 256 thr: (b, y-pair); 128 thr per row
#define COPY_BLOCKS 128
#define W_BLOCKS (FILL_BLOCKS + COPY_BLOCKS + 1)   // +1 loss block

__device__ int   g_assign[NPIX];
__device__ float g_maxcos[NPIX];

// ---- packed fp32x2 helpers (Blackwell FFMA2) ----
__device__ __forceinline__ unsigned long long splat2(float x) {
    unsigned long long r;
    unsigned u = __float_as_uint(x);
    asm("mov.b64 %0, {%1, %2};" : "=l"(r) : "r"(u), "r"(u));
    return r;
}
__device__ __forceinline__ float2 unpack2(unsigned long long v) {
    unsigned lo, hi;
    asm("mov.b64 {%0, %1}, %2;" : "=r"(lo), "=r"(hi) : "l"(v));
    return make_float2(__uint_as_float(lo), __uint_as_float(hi));
}
#define FMA2(d, a, b) \
    asm("fma.rn.f32x2 %0, %1, %2, %0;" : "+l"(d) : "l"(a), "l"(b))

// ---------------------------------------------------------------------------
// simK: cluster norms + cosine sims + per-pixel argmax.
// 256 blocks x 256 thr. Block = 32 px x 64 clusters.
// Thread = 2 px (pid: 16 pairs) x 4 clusters (ng: 16 groups).
// ---------------------------------------------------------------------------
__global__ __launch_bounds__(256) void simK(const float* __restrict__ code,
                                            const float* __restrict__ clusters) {
    const int tid = threadIdx.x;
    const int blk = blockIdx.x;
    const int wid = tid >> 5;
    const int lid = tid & 31;

    __shared__ __align__(16) float codeS[KC][32];
    __shared__ __align__(16) float clusG[16][132];   // [ng][c*4+j], pad->132
    __shared__ float sinv[N_CLUS];

    // cluster inverse norms: warp w -> rows 8w..8w+7, lane-strided + shfl
#pragma unroll
    for (int q = 0; q < 8; ++q) {
        const int n = wid * 8 + q;
        const float* cr = clusters + n * C_DIM;
        float s = 0.f;
#pragma unroll
        for (int i = 0; i < C_DIM / 32; ++i) {
            float v = __ldg(cr + lid + i * 32);
            s = fmaf(v, v, s);
        }
#pragma unroll
        for (int o = 16; o > 0; o >>= 1) s += __shfl_xor_sync(0xffffffffu, s, o);
        if (lid == 0) sinv[n] = 1.f / fmaxf(sqrtf(s), 1e-12f);
    }
    __syncthreads();

    const int b = blk >> 5;                  // 32 blocks per image
    const int hwbase = (blk & 31) * 32;
    const int pid = tid >> 4;                // pixel pair: px 2*pid, 2*pid+1
    const int ng = tid & 15;                 // cluster group: n = 4*ng..4*ng+3
    const float* codeb = code + (size_t)b * C_DIM * HW + hwbase;

    // acc2[p][h]: h=0 packs clusters (4ng+0,4ng+1), h=1 packs (4ng+2,4ng+3)
    unsigned long long acc2[2][2] = {{0ull, 0ull}, {0ull, 0ull}};
    float ssq[2] = {0.f, 0.f};

    for (int c0 = 0; c0 < C_DIM; c0 += KC) {
#pragma unroll
        for (int k = 0; k < 4; ++k) {        // stage code [KC][32], coalesced
            int idx = tid + k * 256;
            int c = idx >> 5, px = idx & 31;
            codeS[c][px] = codeb[(size_t)(c0 + c) * HW + px];
        }
#pragma unroll
        for (int k = 0; k < 8; ++k) {        // stage normed clusters [ng][c][j]
            int idx = tid + k * 256;
            int g = idx >> 7, rr = idx & 127;
            int j = rr & 3, c = rr >> 2;
            int n = g * 4 + j;
            clusG[g][c * 4 + j] = clusters[n * C_DIM + c0 + c] * sinv[n];
        }
        __syncthreads();

#pragma unroll 8
        for (int c = 0; c < KC; ++c) {
            float2 a = *(const float2*)&codeS[c][2 * pid];
            ulonglong2 bp = *(const ulonglong2*)&clusG[ng][4 * c];
            if (ng == 0) {                   // fold feature sumsq into pass
                ssq[0] = fmaf(a.x, a.x, ssq[0]);
                ssq[1] = fmaf(a.y, a.y, ssq[1]);
            }
            unsigned long long ax = splat2(a.x), ay = splat2(a.y);
            FMA2(acc2[0][0], ax, bp.x);  FMA2(acc2[0][1], ax, bp.y);
            FMA2(acc2[1][0], ay, bp.x);  FMA2(acc2[1][1], ay, bp.y);
        }
        __syncthreads();
    }

    // per-pixel argmax: local over 4 clusters, then shfl tree over 16-lane
    // group. Higher lane == higher n; strict '>' keeps first-max tiebreak.
#pragma unroll
    for (int p = 0; p < 2; ++p) {
        float2 j01 = unpack2(acc2[p][0]);
        float2 j23 = unpack2(acc2[p][1]);
        float av[4] = {j01.x, j01.y, j23.x, j23.y};
        float mv = av[0];
        int mn = ng * 4;
#pragma unroll
        for (int j = 1; j < 4; ++j)
            if (av[j] > mv) { mv = av[j]; mn = ng * 4 + j; }
#pragma unroll
        for (int off = 8; off > 0; off >>= 1) {
            float ov = __shfl_down_sync(0xffffffffu, mv, off, 16);
            int   on = __shfl_down_sync(0xffffffffu, mn, off, 16);
            if (ov > mv) { mv = ov; mn = on; }
        }
        if (ng == 0) {
            const int gp = blk * 32 + 2 * pid + p;   // b*1024 + hw index
            g_assign[gp] = mn;
            g_maxcos[gp] = mv / fmaxf(sqrtf(ssq[p]), 1e-12f);
        }
    }
}

// ---------------------------------------------------------------------------
// writeK: phase-split direct write + copy + loss. 256 thr/block.
//   blocks [0,2048):      (b, y-pair). 128 threads per row; thread owns one
//                         aligned float4 slot. Phase A: branchless zero of
//                         its slot across all 64 planes (STG.128, max MLP).
//                         Phase B: overwrite own x's with <=4 scalars each.
//                         Same-thread same-address => ordered, no syncs.
//   blocks [2048,2176):   code passthrough copy
//   block  2176:          deterministic loss reduction
// ---------------------------------------------------------------------------
__global__ __launch_bounds__(256) void writeK(const float* __restrict__ code,
                                              float* __restrict__ out) {
    const int blk = blockIdx.x;
    const int tid = threadIdx.x;

    if (blk >= FILL_BLOCKS) {
        if (blk < FILL_BLOCKS + COPY_BLOCKS) {
            // ---- code passthrough (dst only 4B-aligned; scalar) ----
            const int id = blk - FILL_BLOCKS;
            float* dst = out + 1 + RES_ELEMS;
            for (long long i = (long long)id * 256 + tid;
                 i < (long long)CODE_ELEMS; i += (long long)COPY_BLOCKS * 256)
                dst[i] = __ldg(code + i);
        } else {
            // ---- loss ----
            __shared__ float red[256];
            float s = 0.f;
            for (int i = tid; i < NPIX; i += 256) s += g_maxcos[i];
            red[tid] = s;
            __syncthreads();
            for (int o = 128; o > 0; o >>= 1) {
                if (tid < o) red[tid] += red[tid + o];
                __syncthreads();
            }
            if (tid == 0) out[0] = -red[0] / (float)NPIX;
        }
        return;
    }

    // ---- fill branch: block = (b, 2 rows). warps 0-3 row0, 4-7 row1 ----
    const int b = blk >> 8;                  // 256 blocks per image
    const int y = ((blk & 255) << 1) + (tid >> 7);
    const int t = tid & 127;                 // slot id within row

    float* base = out + 1 + (size_t)b * N_CLUS * PLANE + (size_t)y * OUT_HW;

    // ===== Phase A: branchless zero of this thread's slot, all 64 planes =====
    // t<127: aligned float4 at rel floats [3+4t, 7+4t) (base%4==1 => +3 is
    // 16B-aligned). t==127: edge scalars rel {0,1,2,511}.
    const float4 z4 = make_float4(0.f, 0.f, 0.f, 0.f);
    if (t < 127) {
        float4* p4 = (float4*)(base + 3 + 4 * t);
#pragma unroll 16
        for (int n = 0; n < N_CLUS; ++n)
            __stcs(p4 + (size_t)n * (PLANE / 4), z4);
    } else {
#pragma unroll 8
        for (int n = 0; n < N_CLUS; ++n) {
            float* row = base + (size_t)n * PLANE;
            __stcs(row + 0, 0.f);
            __stcs(row + 1, 0.f);
            __stcs(row + 2, 0.f);
            __stcs(row + 511, 0.f);
        }
    }

    // ===== Phase B: sparse bilinear scatter into own x positions =====
    const float fy = (y + 0.5f) * 0.0625f - 0.5f;
    const float y0f = floorf(fy);
    const float wy1 = fy - y0f, wy0 = 1.f - wy1;
    const int y0 = (int)y0f;
    const int ylo = max(y0, 0), yhi = min(y0 + 1, H_IN - 1);
    const int* A0 = g_assign + b * HW + ylo * H_IN;
    const int* A1 = g_assign + b * HW + yhi * H_IN;

#pragma unroll
    for (int k = 0; k < 4; ++k) {
        const int x = (t < 127) ? (4 * t + 3 + k)
                                : ((k == 3) ? 511 : k);
        const float fx = (x + 0.5f) * 0.0625f - 0.5f;
        const float x0f = floorf(fx);
        const float wx1 = fx - x0f, wx0 = 1.f - wx1;
        const int x0 = (int)x0f;
        const int xlo = max(x0, 0), xhi = min(x0 + 1, H_IN - 1);

        int nn[4]; float w[4];
        nn[0] = __ldg(A0 + xlo); w[0] = wy0 * wx0;
        nn[1] = __ldg(A0 + xhi); w[1] = wy0 * wx1;
        nn[2] = __ldg(A1 + xlo); w[2] = wy1 * wx0;
        nn[3] = __ldg(A1 + xhi); w[3] = wy1 * wx1;

        bool v[4] = {true, true, true, true};
#pragma unroll
        for (int i = 1; i < 4; ++i)
#pragma unroll
            for (int j = 0; j < i; ++j)
                if (v[i] && v[j] && nn[i] == nn[j]) { w[j] += w[i]; v[i] = false; }

#pragma unroll
        for (int i = 0; i < 4; ++i)
            if (v[i]) base[(size_t)nn[i] * PLANE + x] = w[i];
    }
}

// ---------------------------------------------------------------------------
// out layout = [loss(1)] [resized(134217728)] [code(6291456)]
// ---------------------------------------------------------------------------
extern "C" void kernel_launch(void* const* d_in, const int* in_sizes, int n_in,
                              void* d_out, int out_size) {
    const float* code = (const float*)d_in[0];
    const float* clusters = (const float*)d_in[1];
    float* out = (float*)d_out;

    simK<<<256, 256>>>(code, clusters);
    writeK<<<W_BLOCKS, 256>>>(code, out);
}